// round 6
// baseline (speedup 1.0000x reference)
#include <cuda_runtime.h>
#include <cstdint>

// NAM via warp-level tf32 mma.sync.
// inputs (B,F), W1/b1 (F,H), W2 (F,H,H), b2 (F,H), W3 (F,H), b3 (F)
// d_out = [ out (B) | fnn (B,F) ]

#define F_  128
#define H_  64
#define TILE_M 128
#define TPB 256          // 8 warps, one 16-row m-tile each
#define TILES_PER_CTA 8
#define MAX_B 16384

__device__ float g_fnnT[(size_t)F_ * MAX_B];  // fnn transposed (F,B)
__device__ float g_xT[(size_t)F_ * MAX_B];    // inputs transposed (F,B)

__device__ __forceinline__ uint32_t to_tf32(float x) {
    uint32_t u;
    asm("cvt.rna.tf32.f32 %0, %1;" : "=r"(u) : "f"(x));
    return u;
}

__device__ __forceinline__ void mma_tf32(float d[4], const uint32_t a[4],
                                         uint32_t b0, uint32_t b1) {
    asm volatile(
        "mma.sync.aligned.m16n8k8.row.col.f32.tf32.tf32.f32 "
        "{%0,%1,%2,%3}, {%4,%5,%6,%7}, {%8,%9}, {%0,%1,%2,%3};"
        : "+f"(d[0]), "+f"(d[1]), "+f"(d[2]), "+f"(d[3])
        : "r"(a[0]), "r"(a[1]), "r"(a[2]), "r"(a[3]), "r"(b0), "r"(b1));
}

// -------- prep: transpose inputs (B,F) -> g_xT (F,B) --------
__global__ __launch_bounds__(256) void nam_transpose_kernel(
    const float* __restrict__ in, int B)
{
    __shared__ float tile[32][33];
    const int bx = blockIdx.x * 32, fx = blockIdx.y * 32;
    const int tx = threadIdx.x & 31, ty = threadIdx.x >> 5;   // 8 rows/iter
    #pragma unroll
    for (int i = 0; i < 32; i += 8) {
        int r = bx + ty + i;
        tile[ty + i][tx] = (r < B) ? in[(size_t)r * F_ + fx + tx] : 0.0f;
    }
    __syncthreads();
    #pragma unroll
    for (int i = 0; i < 32; i += 8) {
        int b = bx + tx;
        if (b < B) g_xT[(size_t)(fx + ty + i) * B + b] = tile[tx][ty + i];
    }
}

// -------- main: per-feature batched GEMM on tensor cores --------
__global__ __launch_bounds__(TPB, 2) void nam_mma_kernel(
    const float* __restrict__ W1, const float* __restrict__ b1,
    const float* __restrict__ W2, const float* __restrict__ b2,
    const float* __restrict__ W3, const float* __restrict__ b3,
    int B)
{
    // sBfrag[(sp*8 + j)*32 + lane] = uint4{ b0(s=2sp), b1(2sp), b0(2sp+1), b1(2sp+1) }
    //   k-step s, n-tile j: b0 = W2[k=s*8+c][n=j*8+g], b1 = same k+4  (c=lane&3, g=lane>>2)
    __shared__ uint4  sBfrag[4 * 8 * 32];     // 16 KB
    __shared__ float  sW2raw[H_ * H_];        // 16 KB staging
    __shared__ float4 sF1[8 * 32];            // 4 KB: {w1_lo, b1_lo, w1_hi, b1_hi} per (s,lane)
    __shared__ float4 sF3[8 * 32];            // 4 KB: {w3_0, b2_0, w3_1, b2_1}   per (j,lane)
    __shared__ float  sx[TILE_M];

    const int t    = threadIdx.x;
    const int wid  = t >> 5;
    const int lane = t & 31;
    const int c    = lane & 3;
    const int g    = lane >> 2;
    const int f    = blockIdx.y;
    const int cta_base = blockIdx.x * (TILE_M * TILES_PER_CTA);

    // stage W2[f] coalesced
    {
        const float4* gW2 = (const float4*)(W2 + (size_t)f * H_ * H_);
        float4* sr = (float4*)sW2raw;
        #pragma unroll
        for (int i = 0; i < (H_ * H_ / 4) / TPB; i++)     // 4 iters
            sr[t + i * TPB] = gW2[t + i * TPB];
    }
    // fragment constant tables (one entry per thread)
    {
        const float* W1f = W1 + f * H_;
        const float* b1f = b1 + f * H_;
        const float* W3f = W3 + f * H_;
        const float* b2f = b2 + f * H_;
        const int s_ = wid;       // 8 warps <-> 8 s / 8 j
        sF1[s_ * 32 + lane] = make_float4(W1f[s_ * 8 + c],     b1f[s_ * 8 + c],
                                          W1f[s_ * 8 + c + 4], b1f[s_ * 8 + c + 4]);
        sF3[s_ * 32 + lane] = make_float4(W3f[s_ * 8 + 2 * c],     b2f[s_ * 8 + 2 * c],
                                          W3f[s_ * 8 + 2 * c + 1], b2f[s_ * 8 + 2 * c + 1]);
    }
    __syncthreads();
    // scatter W2 into fragment order
    {
        uint32_t* dst = (uint32_t*)sBfrag;
        #pragma unroll
        for (int i = 0; i < (4 * 8 * 32 * 4) / TPB; i++) { // 16 iters
            int idx  = t + i * TPB;
            int q    = idx & 3;
            int ln   = (idx >> 2) & 31;
            int j    = (idx >> 7) & 7;
            int sp   = idx >> 10;
            int s    = 2 * sp + (q >> 1);
            int p    = q & 1;
            int k    = s * 8 + (ln & 3) + 4 * p;
            int n    = j * 8 + (ln >> 2);
            dst[idx] = to_tf32(sW2raw[k * H_ + n]);
        }
    }
    const float b3f = b3[f];
    __syncthreads();

    for (int ti = 0; ti < TILES_PER_CTA; ti++) {
        const int tile_base = cta_base + ti * TILE_M;
        if (tile_base >= B) break;

        if (t < TILE_M) {
            int r = tile_base + t;
            sx[t] = (r < B) ? g_xT[(size_t)f * B + r] : 0.0f;   // coalesced
        }
        __syncthreads();

        const int m0 = wid * 16;
        const float x0 = sx[m0 + g];
        const float x1 = sx[m0 + 8 + g];

        // A fragments: h1 = relu(x*W1 + b1), tf32
        uint32_t a[8][4];
        #pragma unroll
        for (int s = 0; s < 8; s++) {
            const float4 fc = sF1[s * 32 + lane];
            a[s][0] = to_tf32(fmaxf(fmaf(x0, fc.x, fc.y), 0.0f));
            a[s][1] = to_tf32(fmaxf(fmaf(x1, fc.x, fc.y), 0.0f));
            a[s][2] = to_tf32(fmaxf(fmaf(x0, fc.z, fc.w), 0.0f));
            a[s][3] = to_tf32(fmaxf(fmaf(x1, fc.z, fc.w), 0.0f));
        }

        float d[8][4];
        #pragma unroll
        for (int j = 0; j < 8; j++) { d[j][0]=0.f; d[j][1]=0.f; d[j][2]=0.f; d[j][3]=0.f; }

        // sp outer; within sp, sweep j twice -> RAW distance 8 on each d[j]
        #pragma unroll
        for (int sp = 0; sp < 4; sp++) {
            uint4 bv[8];
            #pragma unroll
            for (int j = 0; j < 8; j++) bv[j] = sBfrag[(sp * 8 + j) * 32 + lane];
            #pragma unroll
            for (int j = 0; j < 8; j++) mma_tf32(d[j], a[2 * sp],     bv[j].x, bv[j].y);
            #pragma unroll
            for (int j = 0; j < 8; j++) mma_tf32(d[j], a[2 * sp + 1], bv[j].z, bv[j].w);
        }

        // epilogue: fnn = relu(D + b2) . W3 + b3
        float s0 = 0.f, s1 = 0.f;
        #pragma unroll
        for (int j = 0; j < 8; j++) {
            const float4 fc = sF3[j * 32 + lane];
            s0 = fmaf(fmaxf(d[j][0] + fc.y, 0.f), fc.x, s0);
            s0 = fmaf(fmaxf(d[j][1] + fc.w, 0.f), fc.z, s0);
            s1 = fmaf(fmaxf(d[j][2] + fc.y, 0.f), fc.x, s1);
            s1 = fmaf(fmaxf(d[j][3] + fc.w, 0.f), fc.z, s1);
        }
        s0 += __shfl_xor_sync(0xFFFFFFFFu, s0, 1);
        s0 += __shfl_xor_sync(0xFFFFFFFFu, s0, 2);
        s1 += __shfl_xor_sync(0xFFFFFFFFu, s1, 1);
        s1 += __shfl_xor_sync(0xFFFFFFFFu, s1, 2);

        if (c == 0) {
            const int r0 = tile_base + m0 + g;
            const int r1 = r0 + 8;
            if (r0 < B) g_fnnT[(size_t)f * B + r0] = s0 + b3f;
            if (r1 < B) g_fnnT[(size_t)f * B + r1] = s1 + b3f;
        }
        __syncthreads();
    }
}

// -------- finish: fnnT -> fnn (B,F) + out[b] = sum_f --------
#define FB 64   // batch rows per block
__global__ __launch_bounds__(256) void nam_finish_kernel(
    float* __restrict__ out, float* __restrict__ fnn, int B)
{
    __shared__ float s[F_][FB + 1];
    const int b0 = blockIdx.x * FB;
    const int t  = threadIdx.x;
    const bool full = (b0 + FB <= B);

    if (full) {
        #pragma unroll 2
        for (int i = t; i < F_ * (FB / 4); i += 256) {    // 2048 float4
            int fi = i / (FB / 4), q = i % (FB / 4);
            float4 v = *(const float4*)(&g_fnnT[(size_t)fi * B + b0 + q * 4]);
            s[fi][q * 4 + 0] = v.x; s[fi][q * 4 + 1] = v.y;
            s[fi][q * 4 + 2] = v.z; s[fi][q * 4 + 3] = v.w;
        }
    } else {
        for (int i = t; i < F_ * FB; i += 256) {
            int fi = i / FB, bb = i % FB;
            s[fi][bb] = (b0 + bb < B) ? g_fnnT[(size_t)fi * B + b0 + bb] : 0.0f;
        }
    }
    __syncthreads();

    // write fnn rows: one float4 (4 consecutive f) per thread-iter, coalesced
    for (int i = t; i < FB * (F_ / 4); i += 256) {        // 2048 float4
        int b = i >> 5, q = i & 31;
        if (b0 + b < B) {
            float4 v = make_float4(s[q*4+0][b], s[q*4+1][b], s[q*4+2][b], s[q*4+3][b]);
            *(float4*)(&fnn[(size_t)(b0 + b) * F_ + q * 4]) = v;
        }
    }
    // out: 4 threads per b, each sums 32 features, combine via shfl
    {
        int b  = t >> 2;          // 0..63
        int qq = t & 3;
        float acc = 0.0f;
        #pragma unroll 8
        for (int fc = qq * 32; fc < qq * 32 + 32; fc++) acc += s[fc][b];
        acc += __shfl_xor_sync(0xFFFFFFFFu, acc, 1);
        acc += __shfl_xor_sync(0xFFFFFFFFu, acc, 2);
        if (qq == 0 && b0 + b < B) out[b0 + b] = acc;
    }
}

extern "C" void kernel_launch(void* const* d_in, const int* in_sizes, int n_in,
                              void* d_out, int out_size)
{
    const float* inputs = (const float*)d_in[0];
    const float* W1     = (const float*)d_in[1];
    const float* b1     = (const float*)d_in[2];
    const float* W2     = (const float*)d_in[3];
    const float* b2     = (const float*)d_in[4];
    const float* W3     = (const float*)d_in[5];
    const float* b3     = (const float*)d_in[6];

    const int B = in_sizes[0] / F_;
    float* out = (float*)d_out;
    float* fnn = out + B;

    dim3 tgrid((B + 31) / 32, F_ / 32);
    nam_transpose_kernel<<<tgrid, 256>>>(inputs, B);

    dim3 grid((B + TILE_M * TILES_PER_CTA - 1) / (TILE_M * TILES_PER_CTA), F_);
    nam_mma_kernel<<<grid, TPB>>>(W1, b1, W2, b2, W3, b3, B);

    nam_finish_kernel<<<(B + FB - 1) / FB, 256>>>(out, fnn, B);
}

// round 7
// speedup vs baseline: 1.0568x; 1.0568x over previous
#include <cuda_runtime.h>
#include <cstdint>

// NAM via warp-level tf32 mma.sync.
// inputs (B,F), W1/b1 (F,H), W2 (F,H,H), b2 (F,H), W3 (F,H), b3 (F)
// d_out = [ out (B) | fnn (B,F) ]

#define F_  128
#define H_  64
#define TILE_M 128
#define TPB 256          // 8 warps, one 16-row m-tile each
#define TILES_PER_CTA 8
#define CTA_ROWS (TILE_M * TILES_PER_CTA)   // 1024
#define MAX_B 16384

__device__ float g_fnnT[(size_t)F_ * MAX_B];  // fnn transposed (F,B)

__device__ __forceinline__ uint32_t to_tf32(float x) {
    uint32_t u;
    asm("cvt.rna.tf32.f32 %0, %1;" : "=r"(u) : "f"(x));
    return u;
}

__device__ __forceinline__ void mma_tf32(float d[4], const uint32_t a[4],
                                         uint32_t b0, uint32_t b1) {
    asm volatile(
        "mma.sync.aligned.m16n8k8.row.col.f32.tf32.tf32.f32 "
        "{%0,%1,%2,%3}, {%4,%5,%6,%7}, {%8,%9}, {%0,%1,%2,%3};"
        : "+f"(d[0]), "+f"(d[1]), "+f"(d[2]), "+f"(d[3])
        : "r"(a[0]), "r"(a[1]), "r"(a[2]), "r"(a[3]), "r"(b0), "r"(b1));
}

// -------- main: per-feature batched GEMM on tensor cores --------
__global__ __launch_bounds__(TPB) void nam_mma_kernel(
    const float* __restrict__ inputs,
    const float* __restrict__ W1, const float* __restrict__ b1,
    const float* __restrict__ W2, const float* __restrict__ b2,
    const float* __restrict__ W3, const float* __restrict__ b3,
    int B)
{
    // sBfrag[(j*4 + sp)*32 + lane] = uint4{ b0(s=2sp), b1(2sp), b0(2sp+1), b1(2sp+1) }
    //   n-tile j, k-step s: b0 = W2[k=s*8+c][n=j*8+g], b1 = same k+4  (c=lane&3, g=lane>>2)
    __shared__ uint4  sBfrag[8 * 4 * 32];     // 16 KB
    __shared__ float  sW2raw[H_ * H_];        // 16 KB staging
    __shared__ float4 sF1[8 * 32];            // 4 KB: {w1_lo, b1_lo, w1_hi, b1_hi} per (s,lane)
    __shared__ float4 sF3[8 * 32];            // 4 KB: {w3_0, b2_0, w3_1, b2_1}   per (j,lane)
    __shared__ float  sx[CTA_ROWS];           // 4 KB: x for all 8 tiles

    const int t    = threadIdx.x;
    const int wid  = t >> 5;
    const int lane = t & 31;
    const int c    = lane & 3;
    const int g    = lane >> 2;
    const int f    = blockIdx.y;
    const int cta_base = blockIdx.x * CTA_ROWS;

    // stage W2[f] coalesced
    {
        const float4* gW2 = (const float4*)(W2 + (size_t)f * H_ * H_);
        float4* sr = (float4*)sW2raw;
        #pragma unroll
        for (int i = 0; i < (H_ * H_ / 4) / TPB; i++)     // 4 iters
            sr[t + i * TPB] = gW2[t + i * TPB];
    }
    // fragment constant tables (one entry per thread)
    {
        const float* W1f = W1 + f * H_;
        const float* b1f = b1 + f * H_;
        const float* W3f = W3 + f * H_;
        const float* b2f = b2 + f * H_;
        const int s_ = wid;       // 8 warps <-> 8 s / 8 j
        sF1[s_ * 32 + lane] = make_float4(W1f[s_ * 8 + c],     b1f[s_ * 8 + c],
                                          W1f[s_ * 8 + c + 4], b1f[s_ * 8 + c + 4]);
        sF3[s_ * 32 + lane] = make_float4(W3f[s_ * 8 + 2 * c],     b2f[s_ * 8 + 2 * c],
                                          W3f[s_ * 8 + 2 * c + 1], b2f[s_ * 8 + 2 * c + 1]);
    }
    // x for all tiles of this CTA (strided; inputs is L2-resident)
    #pragma unroll
    for (int i = 0; i < CTA_ROWS / TPB; i++) {            // 4 iters
        int idx = t + i * TPB;
        int r = cta_base + idx;
        sx[idx] = (r < B) ? inputs[(size_t)r * F_ + f] : 0.0f;
    }
    __syncthreads();
    // scatter W2 into fragment order
    {
        uint32_t* dst = (uint32_t*)sBfrag;
        #pragma unroll
        for (int i = 0; i < (8 * 4 * 32 * 4) / TPB; i++) { // 16 iters
            int idx  = t + i * TPB;
            int q    = idx & 3;
            int ln   = (idx >> 2) & 31;
            int sp   = (idx >> 7) & 3;
            int j    = idx >> 9;
            int s    = 2 * sp + (q >> 1);
            int p    = q & 1;
            int k    = s * 8 + (ln & 3) + 4 * p;
            int n    = j * 8 + (ln >> 2);
            dst[idx] = to_tf32(sW2raw[k * H_ + n]);
        }
    }
    const float b3f = b3[f];
    __syncthreads();
    // ---- from here on: NO barriers; warps run free across all tiles ----

    #pragma unroll 1
    for (int ti = 0; ti < TILES_PER_CTA; ti++) {
        const int tile_base = cta_base + ti * TILE_M;
        if (tile_base >= B) break;

        const int m0 = ti * TILE_M + wid * 16;
        const float x0 = sx[m0 + g];
        const float x1 = sx[m0 + 8 + g];

        // A fragments: h1 = relu(x*W1 + b1), tf32
        uint32_t a[8][4];
        #pragma unroll
        for (int s = 0; s < 8; s++) {
            const float4 fc = sF1[s * 32 + lane];
            a[s][0] = to_tf32(fmaxf(fmaf(x0, fc.x, fc.y), 0.0f));
            a[s][1] = to_tf32(fmaxf(fmaf(x1, fc.x, fc.y), 0.0f));
            a[s][2] = to_tf32(fmaxf(fmaf(x0, fc.z, fc.w), 0.0f));
            a[s][3] = to_tf32(fmaxf(fmaf(x1, fc.z, fc.w), 0.0f));
        }

        // D = A @ W2[f]  (8 n-tiles x 8 k-steps), j outer
        float d[8][4];
        #pragma unroll
        for (int j = 0; j < 8; j++) { d[j][0]=0.f; d[j][1]=0.f; d[j][2]=0.f; d[j][3]=0.f; }
        #pragma unroll
        for (int j = 0; j < 8; j++) {
            #pragma unroll
            for (int sp = 0; sp < 4; sp++) {
                const uint4 bv = sBfrag[(j * 4 + sp) * 32 + lane];
                mma_tf32(d[j], a[2 * sp],     bv.x, bv.y);
                mma_tf32(d[j], a[2 * sp + 1], bv.z, bv.w);
            }
        }

        // epilogue: fnn = relu(D + b2) . W3 + b3
        float s0 = 0.f, s1 = 0.f;
        #pragma unroll
        for (int j = 0; j < 8; j++) {
            const float4 fc = sF3[j * 32 + lane];
            s0 = fmaf(fmaxf(d[j][0] + fc.y, 0.f), fc.x, s0);
            s0 = fmaf(fmaxf(d[j][1] + fc.w, 0.f), fc.z, s0);
            s1 = fmaf(fmaxf(d[j][2] + fc.y, 0.f), fc.x, s1);
            s1 = fmaf(fmaxf(d[j][3] + fc.w, 0.f), fc.z, s1);
        }
        s0 += __shfl_xor_sync(0xFFFFFFFFu, s0, 1);
        s0 += __shfl_xor_sync(0xFFFFFFFFu, s0, 2);
        s1 += __shfl_xor_sync(0xFFFFFFFFu, s1, 1);
        s1 += __shfl_xor_sync(0xFFFFFFFFu, s1, 2);

        if (c == 0) {
            const int r0 = tile_base + wid * 16 + g;
            const int r1 = r0 + 8;
            if (r0 < B) g_fnnT[(size_t)f * B + r0] = s0 + b3f;
            if (r1 < B) g_fnnT[(size_t)f * B + r1] = s1 + b3f;
        }
    }
}

// -------- finish: fnnT -> fnn (B,F) + out[b] = sum_f --------
#define FB 64   // batch rows per block
__global__ __launch_bounds__(256) void nam_finish_kernel(
    float* __restrict__ out, float* __restrict__ fnn, int B)
{
    __shared__ float s[F_][FB + 1];
    const int b0 = blockIdx.x * FB;
    const int t  = threadIdx.x;
    const bool full = (b0 + FB <= B);

    if (full) {
        #pragma unroll 2
        for (int i = t; i < F_ * (FB / 4); i += 256) {    // 2048 float4
            int fi = i / (FB / 4), q = i % (FB / 4);
            float4 v = *(const float4*)(&g_fnnT[(size_t)fi * B + b0 + q * 4]);
            s[fi][q * 4 + 0] = v.x; s[fi][q * 4 + 1] = v.y;
            s[fi][q * 4 + 2] = v.z; s[fi][q * 4 + 3] = v.w;
        }
    } else {
        for (int i = t; i < F_ * FB; i += 256) {
            int fi = i / FB, bb = i % FB;
            s[fi][bb] = (b0 + bb < B) ? g_fnnT[(size_t)fi * B + b0 + bb] : 0.0f;
        }
    }
    __syncthreads();

    // write fnn rows: one float4 (4 consecutive f) per thread-iter, coalesced
    for (int i = t; i < FB * (F_ / 4); i += 256) {        // 2048 float4
        int b = i >> 5, q = i & 31;
        if (b0 + b < B) {
            float4 v = make_float4(s[q*4+0][b], s[q*4+1][b], s[q*4+2][b], s[q*4+3][b]);
            *(float4*)(&fnn[(size_t)(b0 + b) * F_ + q * 4]) = v;
        }
    }
    // out: 4 threads per b, each sums 32 features, combine via shfl
    {
        int b  = t >> 2;          // 0..63
        int qq = t & 3;
        float acc = 0.0f;
        #pragma unroll 8
        for (int fc = qq * 32; fc < qq * 32 + 32; fc++) acc += s[fc][b];
        acc += __shfl_xor_sync(0xFFFFFFFFu, acc, 1);
        acc += __shfl_xor_sync(0xFFFFFFFFu, acc, 2);
        if (qq == 0 && b0 + b < B) out[b0 + b] = acc;
    }
}

extern "C" void kernel_launch(void* const* d_in, const int* in_sizes, int n_in,
                              void* d_out, int out_size)
{
    const float* inputs = (const float*)d_in[0];
    const float* W1     = (const float*)d_in[1];
    const float* b1     = (const float*)d_in[2];
    const float* W2     = (const float*)d_in[3];
    const float* b2     = (const float*)d_in[4];
    const float* W3     = (const float*)d_in[5];
    const float* b3     = (const float*)d_in[6];

    const int B = in_sizes[0] / F_;
    float* out = (float*)d_out;
    float* fnn = out + B;

    dim3 grid((B + CTA_ROWS - 1) / CTA_ROWS, F_);
    nam_mma_kernel<<<grid, TPB>>>(inputs, W1, b1, W2, b2, W3, b3, B);

    nam_finish_kernel<<<(B + FB - 1) / FB, 256>>>(out, fnn, B);
}

// round 8
// speedup vs baseline: 1.4746x; 1.3954x over previous
#include <cuda_runtime.h>
#include <cstdint>

// NAM via warp-level fp16 mma.sync m16n8k16 (fp32 accumulate).
// inputs (B,F), W1/b1 (F,H), W2 (F,H,H), b2 (F,H), W3 (F,H), b3 (F)
// d_out = [ out (B) | fnn (B,F) ]

#define F_  128
#define H_  64
#define TILE_M 128
#define TPB 256          // 8 warps, one 16-row m-tile each
#define TILES_PER_CTA 8
#define CTA_ROWS (TILE_M * TILES_PER_CTA)   // 1024

__device__ __forceinline__ uint32_t h2pack(float lo, float hi) {
    uint32_t r;
    asm("cvt.rn.f16x2.f32 %0, %1, %2;" : "=r"(r) : "f"(hi), "f"(lo));  // a=hi half
    return r;
}

__device__ __forceinline__ void mma_f16(float d[4], const uint32_t a[4],
                                        uint32_t b0, uint32_t b1) {
    asm volatile(
        "mma.sync.aligned.m16n8k16.row.col.f32.f16.f16.f32 "
        "{%0,%1,%2,%3}, {%4,%5,%6,%7}, {%8,%9}, {%0,%1,%2,%3};"
        : "+f"(d[0]), "+f"(d[1]), "+f"(d[2]), "+f"(d[3])
        : "r"(a[0]), "r"(a[1]), "r"(a[2]), "r"(a[3]), "r"(b0), "r"(b1));
}

// -------- main: per-feature batched GEMM on fp16 tensor cores --------
__global__ __launch_bounds__(TPB) void nam_mma_kernel(
    const float* __restrict__ inputs,
    const float* __restrict__ W1, const float* __restrict__ b1,
    const float* __restrict__ W2, const float* __restrict__ b2,
    const float* __restrict__ W3, const float* __restrict__ b3,
    float* __restrict__ fnn,
    int B)
{
    // sBfrag[(s*8 + j)*32 + lane] = uint2{ pack(W2[k0][n],W2[k0+1][n]),
    //                                      pack(W2[k0+8][n],W2[k0+9][n]) }
    //   k0 = 16s + 2c, n = 8j + g   (c = lane&3, g = lane>>2)
    __shared__ uint2  sBfrag[4 * 8 * 32];     // 8 KB
    __shared__ float  sW2raw[H_ * H_];        // 16 KB staging
    __shared__ float4 sF1[8 * 32];            // 4 KB: (s,p) -> {W1[k],b1[k],W1[k+1],b1[k+1]}
    __shared__ float4 sF3[8 * 32];            // 4 KB: j -> {W3[n0],b2[n0],W3[n1],b2[n1]}
    __shared__ float  sx[CTA_ROWS];           // 4 KB

    const int t    = threadIdx.x;
    const int wid  = t >> 5;
    const int lane = t & 31;
    const int c    = lane & 3;
    const int g    = lane >> 2;
    const int f    = blockIdx.y;
    const int cta_base = blockIdx.x * CTA_ROWS;

    // stage W2[f] coalesced
    {
        const float4* gW2 = (const float4*)(W2 + (size_t)f * H_ * H_);
        float4* sr = (float4*)sW2raw;
        #pragma unroll
        for (int i = 0; i < (H_ * H_ / 4) / TPB; i++)     // 4 iters
            sr[t + i * TPB] = gW2[t + i * TPB];
    }
    // fragment constant tables (one entry per thread)
    {
        const float* W1f = W1 + f * H_;
        const float* b1f = b1 + f * H_;
        const float* W3f = W3 + f * H_;
        const float* b2f = b2 + f * H_;
        // sF1: idx = (s*2+p)*32 + lane, k = 16s + 2c + 8p
        {
            const int p  = (t >> 5) & 1;
            const int s_ = t >> 6;
            const int k  = 16 * s_ + 2 * c + 8 * p;
            sF1[t] = make_float4(W1f[k], b1f[k], W1f[k + 1], b1f[k + 1]);
        }
        // sF3: idx = j*32 + lane, n = 8j + 2c
        {
            const int j  = t >> 5;
            const int n  = 8 * j + 2 * c;
            sF3[t] = make_float4(W3f[n], b2f[n], W3f[n + 1], b2f[n + 1]);
        }
    }
    // x for all tiles of this CTA
    #pragma unroll
    for (int i = 0; i < CTA_ROWS / TPB; i++) {            // 4 iters
        int idx = t + i * TPB;
        int r = cta_base + idx;
        sx[idx] = (r < B) ? inputs[(size_t)r * F_ + f] : 0.0f;
    }
    __syncthreads();
    // scatter W2 into fp16 fragment order
    {
        #pragma unroll
        for (int i = 0; i < (4 * 8 * 32) / TPB; i++) {    // 4 iters
            int idx = t + i * TPB;
            int ln  = idx & 31;
            int j   = (idx >> 5) & 7;
            int s   = idx >> 8;
            int k0  = 16 * s + 2 * (ln & 3);
            int n   = 8 * j + (ln >> 2);
            uint2 bv;
            bv.x = h2pack(sW2raw[k0 * H_ + n],       sW2raw[(k0 + 1) * H_ + n]);
            bv.y = h2pack(sW2raw[(k0 + 8) * H_ + n], sW2raw[(k0 + 9) * H_ + n]);
            sBfrag[idx] = bv;
        }
    }
    const float b3f = b3[f];
    __syncthreads();
    // ---- no barriers beyond this point ----

    #pragma unroll 1
    for (int ti = 0; ti < TILES_PER_CTA; ti++) {
        const int tile_base = cta_base + ti * TILE_M;
        if (tile_base >= B) break;

        const int m0 = ti * TILE_M + wid * 16;
        const float x0 = sx[m0 + g];
        const float x1 = sx[m0 + 8 + g];

        // A fragments: h1 = relu(x*W1 + b1), fp16-packed
        uint32_t a[4][4];
        #pragma unroll
        for (int s = 0; s < 4; s++) {
            const float4 fA = sF1[(s * 2 + 0) * 32 + lane];   // k = 16s+2c
            const float4 fB = sF1[(s * 2 + 1) * 32 + lane];   // k = 16s+2c+8
            a[s][0] = h2pack(fmaxf(fmaf(x0, fA.x, fA.y), 0.f), fmaxf(fmaf(x0, fA.z, fA.w), 0.f));
            a[s][1] = h2pack(fmaxf(fmaf(x1, fA.x, fA.y), 0.f), fmaxf(fmaf(x1, fA.z, fA.w), 0.f));
            a[s][2] = h2pack(fmaxf(fmaf(x0, fB.x, fB.y), 0.f), fmaxf(fmaf(x0, fB.z, fB.w), 0.f));
            a[s][3] = h2pack(fmaxf(fmaf(x1, fB.x, fB.y), 0.f), fmaxf(fmaf(x1, fB.z, fB.w), 0.f));
        }

        // D = A @ W2[f]: s outer, j inner -> RAW distance 8 on each d[j]
        float d[8][4];
        #pragma unroll
        for (int j = 0; j < 8; j++) { d[j][0]=0.f; d[j][1]=0.f; d[j][2]=0.f; d[j][3]=0.f; }
        #pragma unroll
        for (int s = 0; s < 4; s++) {
            #pragma unroll
            for (int j = 0; j < 8; j++) {
                const uint2 bv = sBfrag[(s * 8 + j) * 32 + lane];
                mma_f16(d[j], a[s], bv.x, bv.y);
            }
        }

        // epilogue: fnn = relu(D + b2) . W3 + b3
        float s0 = 0.f, s1 = 0.f;
        #pragma unroll
        for (int j = 0; j < 8; j++) {
            const float4 fc = sF3[j * 32 + lane];
            s0 = fmaf(fmaxf(d[j][0] + fc.y, 0.f), fc.x, s0);
            s0 = fmaf(fmaxf(d[j][1] + fc.w, 0.f), fc.z, s0);
            s1 = fmaf(fmaxf(d[j][2] + fc.y, 0.f), fc.x, s1);
            s1 = fmaf(fmaxf(d[j][3] + fc.w, 0.f), fc.z, s1);
        }
        s0 += __shfl_xor_sync(0xFFFFFFFFu, s0, 1);
        s0 += __shfl_xor_sync(0xFFFFFFFFu, s0, 2);
        s1 += __shfl_xor_sync(0xFFFFFFFFu, s1, 1);
        s1 += __shfl_xor_sync(0xFFFFFFFFu, s1, 2);

        if (c == 0) {
            const int r0 = tile_base + wid * 16 + g;
            const int r1 = r0 + 8;
            if (r0 < B) fnn[(size_t)r0 * F_ + f] = s0 + b3f;
            if (r1 < B) fnn[(size_t)r1 * F_ + f] = s1 + b3f;
        }
    }
}

// -------- reduce: out[b] = sum_f fnn[b,f]; 2 rows per warp --------
__global__ __launch_bounds__(256) void nam_reduce_kernel(
    const float* __restrict__ fnn, float* __restrict__ out, int B)
{
    const int w    = (blockIdx.x * blockDim.x + threadIdx.x) >> 5;
    const int lane = threadIdx.x & 31;
    const int b0   = w * 2;
    if (b0 >= B) return;

    const float4 v0 = ((const float4*)(fnn + (size_t)b0 * F_))[lane];
    float s0 = (v0.x + v0.y) + (v0.z + v0.w);
    float s1 = 0.0f;
    const bool have1 = (b0 + 1 < B);
    if (have1) {
        const float4 v1 = ((const float4*)(fnn + (size_t)(b0 + 1) * F_))[lane];
        s1 = (v1.x + v1.y) + (v1.z + v1.w);
    }
    #pragma unroll
    for (int o = 16; o > 0; o >>= 1) {
        s0 += __shfl_xor_sync(0xFFFFFFFFu, s0, o);
        s1 += __shfl_xor_sync(0xFFFFFFFFu, s1, o);
    }
    if (lane == 0) {
        out[b0] = s0;
        if (have1) out[b0 + 1] = s1;
    }
}

extern "C" void kernel_launch(void* const* d_in, const int* in_sizes, int n_in,
                              void* d_out, int out_size)
{
    const float* inputs = (const float*)d_in[0];
    const float* W1     = (const float*)d_in[1];
    const float* b1     = (const float*)d_in[2];
    const float* W2     = (const float*)d_in[3];
    const float* b2     = (const float*)d_in[4];
    const float* W3     = (const float*)d_in[5];
    const float* b3     = (const float*)d_in[6];

    const int B = in_sizes[0] / F_;
    float* out = (float*)d_out;
    float* fnn = out + B;

    dim3 grid((B + CTA_ROWS - 1) / CTA_ROWS, F_);
    nam_mma_kernel<<<grid, TPB>>>(inputs, W1, b1, W2, b2, W3, b3, fnn, B);

    const int nwarps  = (B + 1) / 2;
    const int nblocks = (nwarps * 32 + 255) / 256;
    nam_reduce_kernel<<<nblocks, 256>>>(fnn, out, B);
}